// round 2
// baseline (speedup 1.0000x reference)
#include <cuda_runtime.h>
#include <math.h>

#define NB 8192   // batch
#define NE 8      // experts
#define ND 16     // robot_state_size
#define NF 16     // freq bands
#define NH 512    // hidden
#define NG 16     // gate input
#define KF 33     // 2F+1

// ---------------- device scratch (static: allocation-free at launch time) ----
__device__ int   g_cnt[NE];
__device__ int   g_tok[NE][NB];
__device__ float g_gate[NE][NB];
__device__ float g_h[NE][NB][NH];   // per-slot hidden after stage A

// ---------------- init ----------------
__global__ void k_init() {
    if (threadIdx.x < NE) g_cnt[threadIdx.x] = 0;
}

// ---------------- gating: logits -> top2 -> bucket scatter ----------------
__global__ void k_gate(const float* __restrict__ gate_input,
                       const int*   __restrict__ task_ptr,
                       const float* __restrict__ gate_w,
                       const float* __restrict__ gate_b) {
    __shared__ float sw[NG * NE];
    __shared__ float sb[NE];
    int task = task_ptr[0];
    int tid = threadIdx.x;
    if (tid < NG * NE) sw[tid] = gate_w[task * NG * NE + tid];
    if (tid < NE)      sb[tid] = gate_b[task * NE + tid];
    __syncthreads();
    int b = blockIdx.x * blockDim.x + tid;
    if (b >= NB) return;
    float xi[NG];
#pragma unroll
    for (int g = 0; g < NG; g++) xi[g] = gate_input[b * NG + g];
    float lg[NE];
#pragma unroll
    for (int e = 0; e < NE; e++) {
        float a = sb[e];
#pragma unroll
        for (int g = 0; g < NG; g++) a = fmaf(xi[g], sw[g * NE + e], a);
        lg[e] = a;
    }
    // top-2 with lowest-index tie-break (matches jax.lax.top_k)
    int i1 = 0; float l1 = lg[0];
#pragma unroll
    for (int e = 1; e < NE; e++) if (lg[e] > l1) { l1 = lg[e]; i1 = e; }
    int i2 = -1; float l2 = -3.4e38f;
#pragma unroll
    for (int e = 0; e < NE; e++) if (e != i1 && lg[e] > l2) { l2 = lg[e]; i2 = e; }
    // renormalized top-2 softmax == exp(li)/(exp(l1)+exp(l2))
    float t = expf(l2 - l1);
    float inv = 1.0f / (1.0f + t);
    int p1 = atomicAdd(&g_cnt[i1], 1);
    g_tok[i1][p1] = b; g_gate[i1][p1] = inv;
    int p2 = atomicAdd(&g_cnt[i2], 1);
    g_tok[i2][p2] = b; g_gate[i2][p2] = t * inv;
}

// ---------------- stage A: fourier feat -> per-dim linear -> LN -> GELU -> sum_d
#define TMA 32
#define SMEMA_FLOATS (KF*NH + 3*NH + TMA*34 + TMA*ND + 2*TMA*64 + 2*TMA)

__global__ void __launch_bounds__(512, 1) k_expert1(
    const float* __restrict__ expert_input,
    const float* __restrict__ freqs,
    const float* __restrict__ w1,
    const float* __restrict__ b1,
    const float* __restrict__ ln_g,
    const float* __restrict__ ln_b)
{
    int e = blockIdx.y;
    int cnt = g_cnt[e];
    int t0 = blockIdx.x * TMA;
    if (t0 >= cnt) return;

    extern __shared__ float sm[];
    float* s_w    = sm;                    // KF*NH
    float* s_b1   = s_w    + KF * NH;      // NH
    float* s_g    = s_b1   + NH;           // NH
    float* s_lb   = s_g    + NH;           // NH
    float* s_feat = s_lb   + NH;           // TMA*34
    float* s_xi   = s_feat + TMA * 34;     // TMA*ND
    float* s_red  = s_xi   + TMA * ND;     // 2*TMA*64
    float* s_stat = s_red  + 2 * TMA * 64; // TMA*2

    int tid  = threadIdx.x;
    int cg   = tid & 63;   // column group: cols cg*8 .. cg*8+7
    int tg   = tid >> 6;   // token group: tokens tg*4 .. tg*4+3
    int wid  = tid >> 5;
    int lane = tid & 31;

    {   // load xi tile (TMA x ND)
        int t = tid >> 4, dd = tid & 15;
        int idx = t0 + t;
        int bb = g_tok[e][idx < cnt ? idx : (cnt - 1)];
        s_xi[t * ND + dd] = expert_input[bb * ND + dd];
    }

    float hacc[4][8];
#pragma unroll
    for (int i = 0; i < 4; i++)
#pragma unroll
        for (int j = 0; j < 8; j++) hacc[i][j] = 0.0f;

    for (int d = 0; d < ND; d++) {
        __syncthreads();
        {   // stage w1[e][d] (33x512) + per-dim vectors + fourier features
            const float4* wp = (const float4*)(w1 + ((size_t)(e * ND + d)) * (KF * NH));
            float4* swp = (float4*)s_w;
            for (int i = tid; i < (KF * NH) / 4; i += 512) swp[i] = wp[i];
            const float* bp  = b1   + (size_t)(e * ND + d) * NH;
            const float* gp  = ln_g + (size_t)(e * ND + d) * NH;
            const float* lbp = ln_b + (size_t)(e * ND + d) * NH;
            s_b1[tid] = bp[tid];
            s_g[tid]  = gp[tid];
            s_lb[tid] = lbp[tid];
            int t = tid >> 4, f = tid & 15;
            float x  = s_xi[t * ND + d];
            float fr = freqs[(e * ND + d) * NF + f];
            float ang = x * fr * 6.283185307179586f;
            float sv, cv;
            sincosf(ang, &sv, &cv);
            s_feat[t * 34 + f]      = cv;
            s_feat[t * 34 + NF + f] = sv;
            if (f == 0) s_feat[t * 34 + 32] = x;
        }
        __syncthreads();

        float v[4][8];
        {
            const float4* bb = (const float4*)&s_b1[cg * 8];
            float4 b0 = bb[0], b1v = bb[1];
#pragma unroll
            for (int i = 0; i < 4; i++) {
                v[i][0] = b0.x;  v[i][1] = b0.y;  v[i][2] = b0.z;  v[i][3] = b0.w;
                v[i][4] = b1v.x; v[i][5] = b1v.y; v[i][6] = b1v.z; v[i][7] = b1v.w;
            }
        }
#pragma unroll
        for (int f = 0; f < KF; f++) {
            const float4* wr = (const float4*)&s_w[f * NH + cg * 8];
            float4 w0 = wr[0], w1v = wr[1];
            float fv[4];
#pragma unroll
            for (int i = 0; i < 4; i++) fv[i] = s_feat[(tg * 4 + i) * 34 + f];
#pragma unroll
            for (int i = 0; i < 4; i++) {
                v[i][0] = fmaf(fv[i], w0.x,  v[i][0]);
                v[i][1] = fmaf(fv[i], w0.y,  v[i][1]);
                v[i][2] = fmaf(fv[i], w0.z,  v[i][2]);
                v[i][3] = fmaf(fv[i], w0.w,  v[i][3]);
                v[i][4] = fmaf(fv[i], w1v.x, v[i][4]);
                v[i][5] = fmaf(fv[i], w1v.y, v[i][5]);
                v[i][6] = fmaf(fv[i], w1v.z, v[i][6]);
                v[i][7] = fmaf(fv[i], w1v.w, v[i][7]);
            }
        }
        // LN partial sums (per token, over 64 column-threads)
#pragma unroll
        for (int i = 0; i < 4; i++) {
            float s1 = 0.f, s2 = 0.f;
#pragma unroll
            for (int j = 0; j < 8; j++) { s1 += v[i][j]; s2 = fmaf(v[i][j], v[i][j], s2); }
            int tk = tg * 4 + i;
            s_red[tk * 64 + cg]            = s1;
            s_red[TMA * 64 + tk * 64 + cg] = s2;
        }
        __syncthreads();
        // warp w reduces tokens 2w, 2w+1
#pragma unroll
        for (int tt = 0; tt < 2; tt++) {
            int tk = wid * 2 + tt;
            float a = s_red[tk * 64 + lane] + s_red[tk * 64 + 32 + lane];
            float q = s_red[TMA * 64 + tk * 64 + lane] + s_red[TMA * 64 + tk * 64 + 32 + lane];
#pragma unroll
            for (int o = 16; o > 0; o >>= 1) {
                a += __shfl_xor_sync(0xffffffffu, a, o);
                q += __shfl_xor_sync(0xffffffffu, q, o);
            }
            if (lane == 0) {
                float mu  = a * (1.0f / 512.0f);
                float var = q * (1.0f / 512.0f) - mu * mu;
                s_stat[tk * 2]     = mu;
                s_stat[tk * 2 + 1] = rsqrtf(var + 1e-5f);
            }
        }
        __syncthreads();
        {   // LN apply + exact GELU + accumulate over d
            const float4* gg = (const float4*)&s_g[cg * 8];
            const float4* ll = (const float4*)&s_lb[cg * 8];
            float4 g0 = gg[0], g1v = gg[1], l0 = ll[0], l1v = ll[1];
            float gj[8] = {g0.x, g0.y, g0.z, g0.w, g1v.x, g1v.y, g1v.z, g1v.w};
            float lj[8] = {l0.x, l0.y, l0.z, l0.w, l1v.x, l1v.y, l1v.z, l1v.w};
#pragma unroll
            for (int i = 0; i < 4; i++) {
                int tk = tg * 4 + i;
                float mu = s_stat[tk * 2];
                float rs = s_stat[tk * 2 + 1];
#pragma unroll
                for (int j = 0; j < 8; j++) {
                    float nx = fmaf((v[i][j] - mu) * rs, gj[j], lj[j]);
                    hacc[i][j] += 0.5f * nx * (1.0f + erff(nx * 0.7071067811865476f));
                }
            }
        }
    }
#pragma unroll
    for (int i = 0; i < 4; i++) {
        int idx = t0 + tg * 4 + i;
        if (idx < cnt) {
            float* hp = &g_h[e][idx][cg * 8];
            ((float4*)hp)[0] = make_float4(hacc[i][0], hacc[i][1], hacc[i][2], hacc[i][3]);
            ((float4*)hp)[1] = make_float4(hacc[i][4], hacc[i][5], hacc[i][6], hacc[i][7]);
        }
    }
}

// ---------------- stage B: grouped GEMM h @ wo + bo, gated scatter ---------
#define BM 64
#define BN 64
#define BK 16

__global__ void __launch_bounds__(256) k_out(
    const float* __restrict__ wo,
    const float* __restrict__ bo,
    float* __restrict__ out)
{
    int e = blockIdx.z;
    int cnt = g_cnt[e];
    int m0 = blockIdx.x * BM;
    if (m0 >= cnt) return;
    int n0 = blockIdx.y * BN;

    __shared__ float As[BK][BM];
    __shared__ float Bs[BK][BN];

    int tid = threadIdx.x;
    int tx = tid & 15, ty = tid >> 4;
    float acc[4][4];
#pragma unroll
    for (int i = 0; i < 4; i++)
#pragma unroll
        for (int j = 0; j < 4; j++) acc[i][j] = 0.0f;

    const float* wop = wo + (size_t)e * NH * NH;
    int ar = tid >> 2;
    int ac = (tid & 3) * 4;
    int br = tid >> 4;
    int bc = (tid & 15) * 4;

    for (int k0 = 0; k0 < NH; k0 += BK) {
        __syncthreads();
        {
            float4 av;
            int m = m0 + ar;
            if (m < cnt) av = *(const float4*)&g_h[e][m][k0 + ac];
            else         av = make_float4(0.f, 0.f, 0.f, 0.f);
            As[ac + 0][ar] = av.x; As[ac + 1][ar] = av.y;
            As[ac + 2][ar] = av.z; As[ac + 3][ar] = av.w;
            *(float4*)&Bs[br][bc] = *(const float4*)&wop[(size_t)(k0 + br) * NH + n0 + bc];
        }
        __syncthreads();
#pragma unroll
        for (int kk = 0; kk < BK; kk++) {
            float4 a4 = *(const float4*)&As[kk][ty * 4];
            float4 b4 = *(const float4*)&Bs[kk][tx * 4];
            float aa[4] = {a4.x, a4.y, a4.z, a4.w};
            float bb[4] = {b4.x, b4.y, b4.z, b4.w};
#pragma unroll
            for (int i = 0; i < 4; i++)
#pragma unroll
                for (int j = 0; j < 4; j++)
                    acc[i][j] = fmaf(aa[i], bb[j], acc[i][j]);
        }
    }

    const float* bop = bo + e * NH;
#pragma unroll
    for (int i = 0; i < 4; i++) {
        int m = m0 + ty * 4 + i;
        if (m < cnt) {
            int bb = g_tok[e][m];
            float gv = g_gate[e][m];
            float* op = out + (size_t)bb * NH + n0 + tx * 4;
#pragma unroll
            for (int j = 0; j < 4; j++)
                atomicAdd(op + j, gv * (acc[i][j] + bop[n0 + tx * 4 + j]));
        }
    }
}

// ---------------- launch ----------------
extern "C" void kernel_launch(void* const* d_in, const int* in_sizes, int n_in,
                              void* d_out, int out_size) {
    const float* gate_input   = (const float*)d_in[0];
    const float* expert_input = (const float*)d_in[1];
    const int*   task_bh      = (const int*)  d_in[2];
    const float* gate_w       = (const float*)d_in[3];
    const float* gate_b       = (const float*)d_in[4];
    const float* freqs        = (const float*)d_in[5];
    const float* w1           = (const float*)d_in[6];
    const float* b1           = (const float*)d_in[7];
    const float* ln_g         = (const float*)d_in[8];
    const float* ln_b         = (const float*)d_in[9];
    const float* wo           = (const float*)d_in[10];
    const float* bo           = (const float*)d_in[11];
    float* out = (float*)d_out;

    cudaFuncSetAttribute(k_expert1, cudaFuncAttributeMaxDynamicSharedMemorySize,
                         SMEMA_FLOATS * (int)sizeof(float));

    // zero output (also covers the trailing scalar loss = 0)
    cudaMemsetAsync(d_out, 0, (size_t)out_size * sizeof(float), 0);
    k_init<<<1, 32>>>();
    k_gate<<<NB / 256, 256>>>(gate_input, task_bh, gate_w, gate_b);
    k_expert1<<<dim3(NB / TMA, NE), 512, SMEMA_FLOATS * (int)sizeof(float)>>>(
        expert_input, freqs, w1, b1, ln_g, ln_b);
    k_out<<<dim3(NB / BM, NH / BN, NE), 256>>>(wo, bo, out);
}

// round 5
// speedup vs baseline: 1.2166x; 1.2166x over previous
#include <cuda_runtime.h>
#include <math.h>
#include <stdint.h>

#define NB 8192   // batch
#define NE 8      // experts
#define ND 16     // robot_state_size
#define NF 16     // freq bands
#define NH 512    // hidden
#define NG 16     // gate input
#define KF 33     // 2F+1

// ---------------- device scratch ----------------
__device__ int   g_cnt[NE];
__device__ int   g_tok[NE][NB];
__device__ float g_gate[NE][NB];
__device__ float g_h[NE][NB][NH];

// ---------------- init ----------------
__global__ void k_init() {
    if (threadIdx.x < NE) g_cnt[threadIdx.x] = 0;
}

// ---------------- gating ----------------
__global__ void k_gate(const float* __restrict__ gate_input,
                       const int*   __restrict__ task_ptr,
                       const float* __restrict__ gate_w,
                       const float* __restrict__ gate_b) {
    __shared__ float sw[NG * NE];
    __shared__ float sb[NE];
    int task = task_ptr[0];
    int tid = threadIdx.x;
    if (tid < NG * NE) sw[tid] = gate_w[task * NG * NE + tid];
    if (tid < NE)      sb[tid] = gate_b[task * NE + tid];
    __syncthreads();
    int b = blockIdx.x * blockDim.x + tid;
    if (b >= NB) return;
    float xi[NG];
#pragma unroll
    for (int g = 0; g < NG; g++) xi[g] = gate_input[b * NG + g];
    float lg[NE];
#pragma unroll
    for (int e = 0; e < NE; e++) {
        float a = sb[e];
#pragma unroll
        for (int g = 0; g < NG; g++) a = fmaf(xi[g], sw[g * NE + e], a);
        lg[e] = a;
    }
    int i1 = 0; float l1 = lg[0];
#pragma unroll
    for (int e = 1; e < NE; e++) if (lg[e] > l1) { l1 = lg[e]; i1 = e; }
    int i2 = -1; float l2 = -3.4e38f;
#pragma unroll
    for (int e = 0; e < NE; e++) if (e != i1 && lg[e] > l2) { l2 = lg[e]; i2 = e; }
    float t = expf(l2 - l1);
    float inv = 1.0f / (1.0f + t);
    int p1 = atomicAdd(&g_cnt[i1], 1);
    g_tok[i1][p1] = b; g_gate[i1][p1] = inv;
    int p2 = atomicAdd(&g_cnt[i2], 1);
    g_tok[i2][p2] = b; g_gate[i2][p2] = t * inv;
}

// ---------------- cp.async helpers ----------------
__device__ __forceinline__ void cp16(uint32_t dst, const void* src) {
    asm volatile("cp.async.ca.shared.global [%0], [%1], 16;\n" :: "r"(dst), "l"(src));
}
__device__ __forceinline__ void cp_commit() {
    asm volatile("cp.async.commit_group;\n");
}
__device__ __forceinline__ void cp_wait0() {
    asm volatile("cp.async.wait_group 0;\n");
}

// branch-free erf (Abramowitz-Stegun 7.1.26, abs err < 1.5e-7)
__device__ __forceinline__ float erf_fast(float x) {
    float ax = fabsf(x);
    float t = __fdividef(1.0f, fmaf(0.3275911f, ax, 1.0f));
    float p = fmaf(1.061405429f, t, -1.453152027f);
    p = fmaf(p, t, 1.421413741f);
    p = fmaf(p, t, -0.284496736f);
    p = fmaf(p, t, 0.254829592f);
    p = p * t;
    float y = 1.0f - p * __expf(-ax * ax);
    return copysignf(y, x);
}

// ---------------- stage A ----------------
#define TMA 32
#define FPITCH 36
#define WBUF (KF * NH)     // 16896 floats per w buffer
#define VBUF (3 * NH)      // 1536 floats per vec buffer (b1|g|lb)
// layout: w0, w1, v0, v1, feat, xi, part, stat
#define OFF_W0   0
#define OFF_W1   (OFF_W0 + WBUF)
#define OFF_V0   (OFF_W1 + WBUF)
#define OFF_V1   (OFF_V0 + VBUF)
#define OFF_FEAT (OFF_V1 + VBUF)
#define OFF_XI   (OFF_FEAT + KF * FPITCH)
#define OFF_PART (OFF_XI + TMA * ND)
#define OFF_STAT (OFF_PART + 256)
#define SMEMA_FLOATS (OFF_STAT + 64)

__global__ void __launch_bounds__(512, 1) k_expert1(
    const float* __restrict__ expert_input,
    const float* __restrict__ freqs,
    const float* __restrict__ w1,
    const float* __restrict__ b1,
    const float* __restrict__ ln_g,
    const float* __restrict__ ln_b)
{
    int e = blockIdx.y;
    int cnt = g_cnt[e];
    int t0 = blockIdx.x * TMA;
    if (t0 >= cnt) return;

    extern __shared__ float sm[];
    uint32_t smb = (uint32_t)__cvta_generic_to_shared(sm);

    int tid  = threadIdx.x;
    int cg   = tid & 127;  // cols cg*4 .. cg*4+3
    int tg   = tid >> 7;   // tokens tg*8 .. tg*8+7
    int wid  = tid >> 5;
    int lane = tid & 31;

    // prefetch w/vec for d=0 into buffer 0
    {
        const float* wsrc = w1 + (size_t)(e * ND + 0) * WBUF;
        for (int i = tid; i < WBUF / 4; i += 512)
            cp16(smb + (OFF_W0 + i * 4) * 4, wsrc + i * 4);
        if (tid < 128)       cp16(smb + (OFF_V0 + tid * 4) * 4,        b1   + (size_t)(e * ND) * NH + tid * 4);
        else if (tid < 256)  cp16(smb + (OFF_V0 + 512 + (tid-128)*4)*4, ln_g + (size_t)(e * ND) * NH + (tid-128)*4);
        else if (tid < 384)  cp16(smb + (OFF_V0 + 1024 + (tid-256)*4)*4, ln_b + (size_t)(e * ND) * NH + (tid-256)*4);
        cp_commit();
    }

    {   // xi tile
        int t = tid >> 4, dd = tid & 15;
        int idx = t0 + t;
        int bb = g_tok[e][idx < cnt ? idx : (cnt - 1)];
        sm[OFF_XI + t * ND + dd] = expert_input[bb * ND + dd];
    }
    __syncthreads();

    float hacc[8][4];
#pragma unroll
    for (int i = 0; i < 8; i++)
#pragma unroll
        for (int j = 0; j < 4; j++) hacc[i][j] = 0.0f;

    for (int d = 0; d < ND; d++) {
        int buf = d & 1;
        int wof = buf ? OFF_W1 : OFF_W0;
        int vof = buf ? OFF_V1 : OFF_V0;

        cp_wait0();
        {   // fourier features for this d (transposed layout [f][token])
            int t = tid >> 4, f = tid & 15;
            float x  = sm[OFF_XI + t * ND + d];
            float fr = freqs[(e * ND + d) * NF + f];
            float ang = x * fr * 6.283185307179586f;
            float sv, cv;
            sincosf(ang, &sv, &cv);
            sm[OFF_FEAT + f * FPITCH + t]        = cv;
            sm[OFF_FEAT + (NF + f) * FPITCH + t] = sv;
            if (f == 0) sm[OFF_FEAT + 32 * FPITCH + t] = x;
        }
        __syncthreads();

        // prefetch next d (everyone is done with the other buffer now)
        if (d + 1 < ND) {
            int nb = (d + 1) & 1;
            int nwof = nb ? OFF_W1 : OFF_W0;
            int nvof = nb ? OFF_V1 : OFF_V0;
            const float* wsrc = w1 + (size_t)(e * ND + d + 1) * WBUF;
            for (int i = tid; i < WBUF / 4; i += 512)
                cp16(smb + (nwof + i * 4) * 4, wsrc + i * 4);
            if (tid < 128)       cp16(smb + (nvof + tid * 4) * 4,          b1   + (size_t)(e * ND + d + 1) * NH + tid * 4);
            else if (tid < 256)  cp16(smb + (nvof + 512 + (tid-128)*4)*4,  ln_g + (size_t)(e * ND + d + 1) * NH + (tid-128)*4);
            else if (tid < 384)  cp16(smb + (nvof + 1024 + (tid-256)*4)*4, ln_b + (size_t)(e * ND + d + 1) * NH + (tid-256)*4);
        }
        cp_commit();

        // GEMM: v[8 tokens][4 cols]
        float v[8][4];
        {
            float4 b4 = *(const float4*)&sm[vof + cg * 4];
#pragma unroll
            for (int i = 0; i < 8; i++) {
                v[i][0] = b4.x; v[i][1] = b4.y; v[i][2] = b4.z; v[i][3] = b4.w;
            }
        }
#pragma unroll
        for (int f = 0; f < KF; f++) {
            float4 w4 = *(const float4*)&sm[wof + f * NH + cg * 4];
            float4 fa = *(const float4*)&sm[OFF_FEAT + f * FPITCH + tg * 8];
            float4 fb = *(const float4*)&sm[OFF_FEAT + f * FPITCH + tg * 8 + 4];
            float fv[8] = {fa.x, fa.y, fa.z, fa.w, fb.x, fb.y, fb.z, fb.w};
#pragma unroll
            for (int i = 0; i < 8; i++) {
                v[i][0] = fmaf(fv[i], w4.x, v[i][0]);
                v[i][1] = fmaf(fv[i], w4.y, v[i][1]);
                v[i][2] = fmaf(fv[i], w4.z, v[i][2]);
                v[i][3] = fmaf(fv[i], w4.w, v[i][3]);
            }
        }

        // LN partial reduce: shuffle within warp, 4 warp-parts per token
#pragma unroll
        for (int i = 0; i < 8; i++) {
            float s1 = v[i][0] + v[i][1] + v[i][2] + v[i][3];
            float s2 = fmaf(v[i][0], v[i][0], fmaf(v[i][1], v[i][1],
                       fmaf(v[i][2], v[i][2], v[i][3] * v[i][3])));
#pragma unroll
            for (int o = 16; o > 0; o >>= 1) {
                s1 += __shfl_xor_sync(0xffffffffu, s1, o);
                s2 += __shfl_xor_sync(0xffffffffu, s2, o);
            }
            if (lane == 0) {
                int tk = tg * 8 + i;
                sm[OFF_PART + tk * 4 + (wid & 3)]       = s1;
                sm[OFF_PART + 128 + tk * 4 + (wid & 3)] = s2;
            }
        }
        __syncthreads();
        if (tid < 32) {
            float a = sm[OFF_PART + tid * 4] + sm[OFF_PART + tid * 4 + 1]
                    + sm[OFF_PART + tid * 4 + 2] + sm[OFF_PART + tid * 4 + 3];
            float q = sm[OFF_PART + 128 + tid * 4] + sm[OFF_PART + 128 + tid * 4 + 1]
                    + sm[OFF_PART + 128 + tid * 4 + 2] + sm[OFF_PART + 128 + tid * 4 + 3];
            float mu  = a * (1.0f / 512.0f);
            float var = q * (1.0f / 512.0f) - mu * mu;
            sm[OFF_STAT + tid]      = mu;
            sm[OFF_STAT + 32 + tid] = rsqrtf(var + 1e-5f);
        }
        __syncthreads();

        // LN apply + GELU + accumulate
        {
            float4 g4 = *(const float4*)&sm[vof + 512 + cg * 4];
            float4 l4 = *(const float4*)&sm[vof + 1024 + cg * 4];
            float gj[4] = {g4.x, g4.y, g4.z, g4.w};
            float lj[4] = {l4.x, l4.y, l4.z, l4.w};
#pragma unroll
            for (int i = 0; i < 8; i++) {
                int tk = tg * 8 + i;
                float mu = sm[OFF_STAT + tk];
                float rs = sm[OFF_STAT + 32 + tk];
#pragma unroll
                for (int j = 0; j < 4; j++) {
                    float nx = fmaf((v[i][j] - mu) * rs, gj[j], lj[j]);
                    hacc[i][j] += 0.5f * nx * (1.0f + erf_fast(nx * 0.7071067811865476f));
                }
            }
        }
    }

#pragma unroll
    for (int i = 0; i < 8; i++) {
        int idx = t0 + tg * 8 + i;
        if (idx < cnt) {
            *(float4*)&g_h[e][idx][cg * 4] =
                make_float4(hacc[i][0], hacc[i][1], hacc[i][2], hacc[i][3]);
        }
    }
}

// ---------------- stage B: 128x128x8, 8x8 microtile ----------------
#define BM 128
#define BN 128
#define BK 8

__global__ void __launch_bounds__(256) k_out(
    const float* __restrict__ wo,
    const float* __restrict__ bo,
    float* __restrict__ out)
{
    int e = blockIdx.z;
    int cnt = g_cnt[e];
    int m0 = blockIdx.x * BM;
    if (m0 >= cnt) return;
    int n0 = blockIdx.y * BN;

    __shared__ float As[BK][BM];
    __shared__ float Bs[BK][BN];

    int tid = threadIdx.x;
    int tx = tid & 15;   // n: tx*8..+8
    int ty = tid >> 4;   // m: ty*8..+8

    float acc[8][8];
#pragma unroll
    for (int i = 0; i < 8; i++)
#pragma unroll
        for (int j = 0; j < 8; j++) acc[i][j] = 0.0f;

    const float* wop = wo + (size_t)e * NH * NH;
    int am = tid & 127;          // A: row m, k-chunk
    int ak = (tid >> 7) * 4;
    int br = tid >> 5;           // B: row k, col chunk
    int bc = (tid & 31) * 4;

    for (int k0 = 0; k0 < NH; k0 += BK) {
        __syncthreads();
        {
            float4 av;
            int m = m0 + am;
            if (m < cnt) av = *(const float4*)&g_h[e][m][k0 + ak];
            else         av = make_float4(0.f, 0.f, 0.f, 0.f);
            As[ak + 0][am] = av.x; As[ak + 1][am] = av.y;
            As[ak + 2][am] = av.z; As[ak + 3][am] = av.w;
            *(float4*)&Bs[br][bc] = *(const float4*)&wop[(size_t)(k0 + br) * NH + n0 + bc];
        }
        __syncthreads();
#pragma unroll
        for (int kk = 0; kk < BK; kk++) {
            float4 a0 = *(const float4*)&As[kk][ty * 8];
            float4 a1 = *(const float4*)&As[kk][ty * 8 + 4];
            float4 b0 = *(const float4*)&Bs[kk][tx * 8];
            float4 b1v = *(const float4*)&Bs[kk][tx * 8 + 4];
            float aa[8] = {a0.x, a0.y, a0.z, a0.w, a1.x, a1.y, a1.z, a1.w};
            float bb[8] = {b0.x, b0.y, b0.z, b0.w, b1v.x, b1v.y, b1v.z, b1v.w};
#pragma unroll
            for (int i = 0; i < 8; i++)
#pragma unroll
                for (int j = 0; j < 8; j++)
                    acc[i][j] = fmaf(aa[i], bb[j], acc[i][j]);
        }
    }

    float bv[8];
#pragma unroll
    for (int j = 0; j < 8; j++) bv[j] = bo[e * NH + n0 + tx * 8 + j];

#pragma unroll
    for (int i = 0; i < 8; i++) {
        int m = m0 + ty * 8 + i;
        if (m < cnt) {
            int bb = g_tok[e][m];
            float gv = g_gate[e][m];
            float* op = out + (size_t)bb * NH + n0 + tx * 8;
#pragma unroll
            for (int j = 0; j < 8; j++)
                atomicAdd(op + j, gv * (acc[i][j] + bv[j]));
        }
    }
}

// ---------------- launch ----------------
extern "C" void kernel_launch(void* const* d_in, const int* in_sizes, int n_in,
                              void* d_out, int out_size) {
    const float* gate_input   = (const float*)d_in[0];
    const float* expert_input = (const float*)d_in[1];
    const int*   task_bh      = (const int*)  d_in[2];
    const float* gate_w       = (const float*)d_in[3];
    const float* gate_b       = (const float*)d_in[4];
    const float* freqs        = (const float*)d_in[5];
    const float* w1           = (const float*)d_in[6];
    const float* b1           = (const float*)d_in[7];
    const float* ln_g         = (const float*)d_in[8];
    const float* ln_b         = (const float*)d_in[9];
    const float* wo           = (const float*)d_in[10];
    const float* bo           = (const float*)d_in[11];
    float* out = (float*)d_out;

    cudaFuncSetAttribute(k_expert1, cudaFuncAttributeMaxDynamicSharedMemorySize,
                         SMEMA_FLOATS * (int)sizeof(float));

    cudaMemsetAsync(d_out, 0, (size_t)out_size * sizeof(float), 0);
    k_init<<<1, 32>>>();
    k_gate<<<NB / 256, 256>>>(gate_input, task_bh, gate_w, gate_b);
    k_expert1<<<dim3(NB / TMA, NE), 512, SMEMA_FLOATS * (int)sizeof(float)>>>(
        expert_input, freqs, w1, b1, ln_g, ln_b);
    k_out<<<dim3(NB / BM, NH / BN, NE), 256>>>(wo, bo, out);
}

// round 9
// speedup vs baseline: 1.3798x; 1.1341x over previous
#include <cuda_runtime.h>
#include <math.h>
#include <stdint.h>

#define NB 8192   // batch
#define NE 8      // experts
#define ND 16     // robot_state_size
#define NF 16     // freq bands
#define NH 512    // hidden
#define NG 16     // gate input
#define KF 33     // 2F+1

// ---------------- device scratch ----------------
__device__ int   g_cnt[NE];
__device__ int   g_tok[NE][NB];
__device__ float g_gate[NE][NB];
__device__ float g_h[NE][NB][NH];

// ---------------- init ----------------
__global__ void k_init() {
    if (threadIdx.x < NE) g_cnt[threadIdx.x] = 0;
}

// ---------------- gating ----------------
__global__ void k_gate(const float* __restrict__ gate_input,
                       const int*   __restrict__ task_ptr,
                       const float* __restrict__ gate_w,
                       const float* __restrict__ gate_b) {
    __shared__ float sw[NG * NE];
    __shared__ float sb[NE];
    int task = task_ptr[0];
    int tid = threadIdx.x;
    if (tid < NG * NE) sw[tid] = gate_w[task * NG * NE + tid];
    if (tid < NE)      sb[tid] = gate_b[task * NE + tid];
    __syncthreads();
    int b = blockIdx.x * blockDim.x + tid;
    if (b >= NB) return;
    float xi[NG];
#pragma unroll
    for (int g = 0; g < NG; g++) xi[g] = gate_input[b * NG + g];
    float lg[NE];
#pragma unroll
    for (int e = 0; e < NE; e++) {
        float a = sb[e];
#pragma unroll
        for (int g = 0; g < NG; g++) a = fmaf(xi[g], sw[g * NE + e], a);
        lg[e] = a;
    }
    int i1 = 0; float l1 = lg[0];
#pragma unroll
    for (int e = 1; e < NE; e++) if (lg[e] > l1) { l1 = lg[e]; i1 = e; }
    int i2 = -1; float l2 = -3.4e38f;
#pragma unroll
    for (int e = 0; e < NE; e++) if (e != i1 && lg[e] > l2) { l2 = lg[e]; i2 = e; }
    float t = expf(l2 - l1);
    float inv = 1.0f / (1.0f + t);
    int p1 = atomicAdd(&g_cnt[i1], 1);
    g_tok[i1][p1] = b; g_gate[i1][p1] = inv;
    int p2 = atomicAdd(&g_cnt[i2], 1);
    g_tok[i2][p2] = b; g_gate[i2][p2] = t * inv;
}

// ---------------- cp.async helpers ----------------
__device__ __forceinline__ void cp16(uint32_t dst, const void* src) {
    asm volatile("cp.async.ca.shared.global [%0], [%1], 16;\n" :: "r"(dst), "l"(src));
}
__device__ __forceinline__ void cp_commit() {
    asm volatile("cp.async.commit_group;\n");
}
__device__ __forceinline__ void cp_wait0() {
    asm volatile("cp.async.wait_group 0;\n");
}

// GELU via HW tanh: 0.5x(1+tanh(0.79788456 x (1+0.044715 x^2)))
__device__ __forceinline__ float gelu_tanh(float x) {
    float x2 = x * x;
    float u = x * fmaf(0.0356774081f, x2, 0.7978845608f);
    float t;
    asm("tanh.approx.f32 %0, %1;" : "=f"(t) : "f"(u));
    return 0.5f * x * (1.0f + t);
}

// ---------------- stage A ----------------
#define TMA 32
#define FPITCH 36
#define WBUF (KF * NH)     // 16896 floats per w buffer
#define VBUF (3 * NH)      // 1536 floats per vec buffer (b1|g|lb)
#define OFF_W0   0
#define OFF_W1   (OFF_W0 + WBUF)
#define OFF_V0   (OFF_W1 + WBUF)
#define OFF_V1   (OFF_V0 + VBUF)
#define OFF_FEAT (OFF_V1 + VBUF)
#define OFF_XI   (OFF_FEAT + KF * FPITCH)
#define OFF_PART (OFF_XI + TMA * ND)
#define OFF_STAT (OFF_PART + 256)
#define SMEMA_FLOATS (OFF_STAT + 64)

__global__ void __launch_bounds__(512, 1) k_expert1(
    const float* __restrict__ expert_input,
    const float* __restrict__ freqs,
    const float* __restrict__ w1,
    const float* __restrict__ b1,
    const float* __restrict__ ln_g,
    const float* __restrict__ ln_b)
{
    int e = blockIdx.y;
    int cnt = g_cnt[e];
    int t0 = blockIdx.x * TMA;
    if (t0 >= cnt) return;

    extern __shared__ float sm[];
    uint32_t smb = (uint32_t)__cvta_generic_to_shared(sm);

    int tid  = threadIdx.x;
    int cg   = tid & 127;  // cols cg*4 .. cg*4+3
    int tg   = tid >> 7;   // tokens tg*8 .. tg*8+7
    int wid  = tid >> 5;
    int lane = tid & 31;

    // prefetch w/vec for d=0 into buffer 0
    {
        const float* wsrc = w1 + (size_t)(e * ND + 0) * WBUF;
        for (int i = tid; i < WBUF / 4; i += 512)
            cp16(smb + (OFF_W0 + i * 4) * 4, wsrc + i * 4);
        if (tid < 128)       cp16(smb + (OFF_V0 + tid * 4) * 4,        b1   + (size_t)(e * ND) * NH + tid * 4);
        else if (tid < 256)  cp16(smb + (OFF_V0 + 512 + (tid-128)*4)*4, ln_g + (size_t)(e * ND) * NH + (tid-128)*4);
        else if (tid < 384)  cp16(smb + (OFF_V0 + 1024 + (tid-256)*4)*4, ln_b + (size_t)(e * ND) * NH + (tid-256)*4);
        cp_commit();
    }

    {   // xi tile
        int t = tid >> 4, dd = tid & 15;
        int idx = t0 + t;
        int bb = g_tok[e][idx < cnt ? idx : (cnt - 1)];
        sm[OFF_XI + t * ND + dd] = expert_input[bb * ND + dd];
    }
    __syncthreads();

    float hacc[8][4];
#pragma unroll
    for (int i = 0; i < 8; i++)
#pragma unroll
        for (int j = 0; j < 4; j++) hacc[i][j] = 0.0f;

    for (int d = 0; d < ND; d++) {
        int buf = d & 1;
        int wof = buf ? OFF_W1 : OFF_W0;
        int vof = buf ? OFF_V1 : OFF_V0;

        cp_wait0();
        {   // fourier features for this d (transposed layout [f][token])
            int t = tid >> 4, f = tid & 15;
            float x  = sm[OFF_XI + t * ND + d];
            float fr = freqs[(e * ND + d) * NF + f];
            float ang = x * fr * 6.283185307179586f;
            float sv, cv;
            sincosf(ang, &sv, &cv);
            sm[OFF_FEAT + f * FPITCH + t]        = cv;
            sm[OFF_FEAT + (NF + f) * FPITCH + t] = sv;
            if (f == 0) sm[OFF_FEAT + 32 * FPITCH + t] = x;
        }
        __syncthreads();

        // prefetch next d
        if (d + 1 < ND) {
            int nb = (d + 1) & 1;
            int nwof = nb ? OFF_W1 : OFF_W0;
            int nvof = nb ? OFF_V1 : OFF_V0;
            const float* wsrc = w1 + (size_t)(e * ND + d + 1) * WBUF;
            for (int i = tid; i < WBUF / 4; i += 512)
                cp16(smb + (nwof + i * 4) * 4, wsrc + i * 4);
            if (tid < 128)       cp16(smb + (nvof + tid * 4) * 4,          b1   + (size_t)(e * ND + d + 1) * NH + tid * 4);
            else if (tid < 256)  cp16(smb + (nvof + 512 + (tid-128)*4)*4,  ln_g + (size_t)(e * ND + d + 1) * NH + (tid-128)*4);
            else if (tid < 384)  cp16(smb + (nvof + 1024 + (tid-256)*4)*4, ln_b + (size_t)(e * ND + d + 1) * NH + (tid-256)*4);
        }
        cp_commit();

        // GEMM: v[8 tokens][4 cols]
        float v[8][4];
        {
            float4 b4 = *(const float4*)&sm[vof + cg * 4];
#pragma unroll
            for (int i = 0; i < 8; i++) {
                v[i][0] = b4.x; v[i][1] = b4.y; v[i][2] = b4.z; v[i][3] = b4.w;
            }
        }
#pragma unroll
        for (int f = 0; f < KF; f++) {
            float4 w4 = *(const float4*)&sm[wof + f * NH + cg * 4];
            float4 fa = *(const float4*)&sm[OFF_FEAT + f * FPITCH + tg * 8];
            float4 fb = *(const float4*)&sm[OFF_FEAT + f * FPITCH + tg * 8 + 4];
            float fv[8] = {fa.x, fa.y, fa.z, fa.w, fb.x, fb.y, fb.z, fb.w};
#pragma unroll
            for (int i = 0; i < 8; i++) {
                v[i][0] = fmaf(fv[i], w4.x, v[i][0]);
                v[i][1] = fmaf(fv[i], w4.y, v[i][1]);
                v[i][2] = fmaf(fv[i], w4.z, v[i][2]);
                v[i][3] = fmaf(fv[i], w4.w, v[i][3]);
            }
        }

        // LN partial reduce
#pragma unroll
        for (int i = 0; i < 8; i++) {
            float s1 = v[i][0] + v[i][1] + v[i][2] + v[i][3];
            float s2 = fmaf(v[i][0], v[i][0], fmaf(v[i][1], v[i][1],
                       fmaf(v[i][2], v[i][2], v[i][3] * v[i][3])));
#pragma unroll
            for (int o = 16; o > 0; o >>= 1) {
                s1 += __shfl_xor_sync(0xffffffffu, s1, o);
                s2 += __shfl_xor_sync(0xffffffffu, s2, o);
            }
            if (lane == 0) {
                int tk = tg * 8 + i;
                sm[OFF_PART + tk * 4 + (wid & 3)]       = s1;
                sm[OFF_PART + 128 + tk * 4 + (wid & 3)] = s2;
            }
        }
        __syncthreads();
        if (tid < 32) {
            float a = sm[OFF_PART + tid * 4] + sm[OFF_PART + tid * 4 + 1]
                    + sm[OFF_PART + tid * 4 + 2] + sm[OFF_PART + tid * 4 + 3];
            float q = sm[OFF_PART + 128 + tid * 4] + sm[OFF_PART + 128 + tid * 4 + 1]
                    + sm[OFF_PART + 128 + tid * 4 + 2] + sm[OFF_PART + 128 + tid * 4 + 3];
            float mu  = a * (1.0f / 512.0f);
            float var = q * (1.0f / 512.0f) - mu * mu;
            sm[OFF_STAT + tid]      = mu;
            sm[OFF_STAT + 32 + tid] = rsqrtf(var + 1e-5f);
        }
        __syncthreads();

        // LN apply + GELU + accumulate
        {
            float4 g4 = *(const float4*)&sm[vof + 512 + cg * 4];
            float4 l4 = *(const float4*)&sm[vof + 1024 + cg * 4];
            float gj[4] = {g4.x, g4.y, g4.z, g4.w};
            float lj[4] = {l4.x, l4.y, l4.z, l4.w};
#pragma unroll
            for (int i = 0; i < 8; i++) {
                int tk = tg * 8 + i;
                float mu = sm[OFF_STAT + tk];
                float rs = sm[OFF_STAT + 32 + tk];
#pragma unroll
                for (int j = 0; j < 4; j++) {
                    float nx = fmaf((v[i][j] - mu) * rs, gj[j], lj[j]);
                    hacc[i][j] += gelu_tanh(nx);
                }
            }
        }
    }

#pragma unroll
    for (int i = 0; i < 8; i++) {
        int idx = t0 + tg * 8 + i;
        if (idx < cnt) {
            *(float4*)&g_h[e][idx][cg * 4] =
                make_float4(hacc[i][0], hacc[i][1], hacc[i][2], hacc[i][3]);
        }
    }
}

// ---------------- stage B: pipelined 128x128x16, double-buffered ----------
#define BM 128
#define BN 128
#define BK 16
#define NIT (NH / BK)   // 32

__global__ void __launch_bounds__(256, 2) k_out(
    const float* __restrict__ wo,
    const float* __restrict__ bo,
    float* __restrict__ out)
{
    int e = blockIdx.z;
    int cnt = g_cnt[e];
    int m0 = blockIdx.x * BM;
    if (m0 >= cnt) return;
    int n0 = blockIdx.y * BN;

    __shared__ float As[2][BK][BM];   // 16 KB
    __shared__ float Bs[2][BK][BN];   // 16 KB

    int tid = threadIdx.x;
    int tx = tid & 15;   // n: tx*8..+8
    int ty = tid >> 4;   // m: ty*8..+8

    // A: thread loads rows am, cols k0+aq..+8 (2 float4)
    int am = tid & 127;
    int aq = (tid >> 7) * 8;
    int amG = m0 + am;
    bool amOK = amG < cnt;
    const float* aptr = &g_h[e][amOK ? amG : 0][aq];
    // B: thread loads row bk, cols bc..+8 (2 float4)
    int bk = tid >> 4;
    int bc = (tid & 15) * 8;
    const float* bptr = wo + (size_t)e * NH * NH + (size_t)bk * NH + n0 + bc;

    float4 pa0, pa1, pb0, pb1;
    // prologue: load k0 = 0
    if (amOK) { pa0 = *(const float4*)(aptr);  pa1 = *(const float4*)(aptr + 4); }
    else      { pa0 = make_float4(0,0,0,0);    pa1 = pa0; }
    pb0 = *(const float4*)(bptr);
    pb1 = *(const float4*)(bptr + 4);
    {
        As[0][aq + 0][am] = pa0.x; As[0][aq + 1][am] = pa0.y;
        As[0][aq + 2][am] = pa0.z; As[0][aq + 3][am] = pa0.w;
        As[0][aq + 4][am] = pa1.x; As[0][aq + 5][am] = pa1.y;
        As[0][aq + 6][am] = pa1.z; As[0][aq + 7][am] = pa1.w;
        *(float4*)&Bs[0][bk][bc]     = pb0;
        *(float4*)&Bs[0][bk][bc + 4] = pb1;
    }
    __syncthreads();

    float acc[8][8];
#pragma unroll
    for (int i = 0; i < 8; i++)
#pragma unroll
        for (int j = 0; j < 8; j++) acc[i][j] = 0.0f;

    for (int it = 0; it < NIT; it++) {
        int cur = it & 1;
        if (it + 1 < NIT) {   // prefetch next tile into registers
            int k0 = (it + 1) * BK;
            if (amOK) { pa0 = *(const float4*)(aptr + k0);  pa1 = *(const float4*)(aptr + k0 + 4); }
            pb0 = *(const float4*)(bptr + (size_t)k0 * NH);
            pb1 = *(const float4*)(bptr + (size_t)k0 * NH + 4);
        }
#pragma unroll
        for (int kk = 0; kk < BK; kk++) {
            float4 a0 = *(const float4*)&As[cur][kk][ty * 8];
            float4 a1 = *(const float4*)&As[cur][kk][ty * 8 + 4];
            float4 b0 = *(const float4*)&Bs[cur][kk][tx * 8];
            float4 b1v = *(const float4*)&Bs[cur][kk][tx * 8 + 4];
            float aa[8] = {a0.x, a0.y, a0.z, a0.w, a1.x, a1.y, a1.z, a1.w};
            float bb[8] = {b0.x, b0.y, b0.z, b0.w, b1v.x, b1v.y, b1v.z, b1v.w};
#pragma unroll
            for (int i = 0; i < 8; i++)
#pragma unroll
                for (int j = 0; j < 8; j++)
                    acc[i][j] = fmaf(aa[i], bb[j], acc[i][j]);
        }
        if (it + 1 < NIT) {
            int nxt = cur ^ 1;
            As[nxt][aq + 0][am] = pa0.x; As[nxt][aq + 1][am] = pa0.y;
            As[nxt][aq + 2][am] = pa0.z; As[nxt][aq + 3][am] = pa0.w;
            As[nxt][aq + 4][am] = pa1.x; As[nxt][aq + 5][am] = pa1.y;
            As[nxt][aq + 6][am] = pa1.z; As[nxt][aq + 7][am] = pa1.w;
            *(float4*)&Bs[nxt][bk][bc]     = pb0;
            *(float4*)&Bs[nxt][bk][bc + 4] = pb1;
            __syncthreads();
        }
    }

    float bv[8];
#pragma unroll
    for (int j = 0; j < 8; j++) bv[j] = bo[e * NH + n0 + tx * 8 + j];

#pragma unroll
    for (int i = 0; i < 8; i++) {
        int m = m0 + ty * 8 + i;
        if (m < cnt) {
            int bb = g_tok[e][m];
            float gv = g_gate[e][m];
            float* op = out + (size_t)bb * NH + n0 + tx * 8;
#pragma unroll
            for (int j = 0; j < 8; j++)
                atomicAdd(op + j, gv * (acc[i][j] + bv[j]));
        }
    }
}

// ---------------- launch ----------------
extern "C" void kernel_launch(void* const* d_in, const int* in_sizes, int n_in,
                              void* d_out, int out_size) {
    const float* gate_input   = (const float*)d_in[0];
    const float* expert_input = (const float*)d_in[1];
    const int*   task_bh      = (const int*)  d_in[2];
    const float* gate_w       = (const float*)d_in[3];
    const float* gate_b       = (const float*)d_in[4];
    const float* freqs        = (const float*)d_in[5];
    const float* w1           = (const float*)d_in[6];
    const float* b1           = (const float*)d_in[7];
    const float* ln_g         = (const float*)d_in[8];
    const float* ln_b         = (const float*)d_in[9];
    const float* wo           = (const float*)d_in[10];
    const float* bo           = (const float*)d_in[11];
    float* out = (float*)d_out;

    cudaFuncSetAttribute(k_expert1, cudaFuncAttributeMaxDynamicSharedMemorySize,
                         SMEMA_FLOATS * (int)sizeof(float));

    cudaMemsetAsync(d_out, 0, (size_t)out_size * sizeof(float), 0);
    k_init<<<1, 32>>>();
    k_gate<<<NB / 256, 256>>>(gate_input, task_bh, gate_w, gate_b);
    k_expert1<<<dim3(NB / TMA, NE), 512, SMEMA_FLOATS * (int)sizeof(float)>>>(
        expert_input, freqs, w1, b1, ln_g, ln_b);
    k_out<<<dim3(NB / BM, NH / BN, NE), 256>>>(wo, bo, out);
}

// round 12
// speedup vs baseline: 1.4280x; 1.0350x over previous
#include <cuda_runtime.h>
#include <math.h>
#include <stdint.h>

#define NB 8192   // batch
#define NE 8      // experts
#define ND 16     // robot_state_size
#define NF 16     // freq bands
#define NH 512    // hidden
#define NG 16     // gate input
#define KF 33     // 2F+1

typedef unsigned long long u64;

// ---------------- f32x2 packed helpers (sm_103a FFMA2) ----------------
__device__ __forceinline__ u64 pk2(float x, float y) {
    u64 r; asm("mov.b64 %0, {%1, %2};" : "=l"(r) : "f"(x), "f"(y)); return r;
}
__device__ __forceinline__ void upk2(u64 v, float& x, float& y) {
    asm("mov.b64 {%0, %1}, %2;" : "=f"(x), "=f"(y) : "l"(v));
}
__device__ __forceinline__ void fma2(u64& d, u64 a, u64 b) {
    asm("fma.rn.f32x2 %0, %1, %2, %0;" : "+l"(d) : "l"(a), "l"(b));
}

// ---------------- device scratch ----------------
__device__ int   g_cnt[NE];
__device__ int   g_tok[NE][NB];
__device__ float g_gate[NE][NB];
__device__ float g_h[NE][NB][NH];

// ---------------- init ----------------
__global__ void k_init() {
    if (threadIdx.x < NE) g_cnt[threadIdx.x] = 0;
}

// ---------------- gating ----------------
__global__ void k_gate(const float* __restrict__ gate_input,
                       const int*   __restrict__ task_ptr,
                       const float* __restrict__ gate_w,
                       const float* __restrict__ gate_b) {
    __shared__ float sw[NG * NE];
    __shared__ float sb[NE];
    int task = task_ptr[0];
    int tid = threadIdx.x;
    if (tid < NG * NE) sw[tid] = gate_w[task * NG * NE + tid];
    if (tid < NE)      sb[tid] = gate_b[task * NE + tid];
    __syncthreads();
    int b = blockIdx.x * blockDim.x + tid;
    if (b >= NB) return;
    float xi[NG];
#pragma unroll
    for (int g = 0; g < NG; g++) xi[g] = gate_input[b * NG + g];
    float lg[NE];
#pragma unroll
    for (int e = 0; e < NE; e++) {
        float a = sb[e];
#pragma unroll
        for (int g = 0; g < NG; g++) a = fmaf(xi[g], sw[g * NE + e], a);
        lg[e] = a;
    }
    int i1 = 0; float l1 = lg[0];
#pragma unroll
    for (int e = 1; e < NE; e++) if (lg[e] > l1) { l1 = lg[e]; i1 = e; }
    int i2 = -1; float l2 = -3.4e38f;
#pragma unroll
    for (int e = 0; e < NE; e++) if (e != i1 && lg[e] > l2) { l2 = lg[e]; i2 = e; }
    float t = expf(l2 - l1);
    float inv = 1.0f / (1.0f + t);
    int p1 = atomicAdd(&g_cnt[i1], 1);
    g_tok[i1][p1] = b; g_gate[i1][p1] = inv;
    int p2 = atomicAdd(&g_cnt[i2], 1);
    g_tok[i2][p2] = b; g_gate[i2][p2] = t * inv;
}

// ---------------- cp.async helpers ----------------
__device__ __forceinline__ void cp16(uint32_t dst, const void* src) {
    asm volatile("cp.async.ca.shared.global [%0], [%1], 16;\n" :: "r"(dst), "l"(src));
}
__device__ __forceinline__ void cp_commit() {
    asm volatile("cp.async.commit_group;\n");
}
__device__ __forceinline__ void cp_wait0() {
    asm volatile("cp.async.wait_group 0;\n");
}

// GELU via HW tanh
__device__ __forceinline__ float gelu_tanh(float x) {
    float x2 = x * x;
    float u = x * fmaf(0.0356774081f, x2, 0.7978845608f);
    float t;
    asm("tanh.approx.f32 %0, %1;" : "=f"(t) : "f"(u));
    return 0.5f * x * (1.0f + t);
}

// ---------------- stage A ----------------
#define TMA 32
#define FPITCH 36
#define WBUF (KF * NH)     // 16896 floats per w buffer
#define VBUF (3 * NH)      // 1536 floats per vec buffer (b1|g|lb)
#define OFF_W0   0
#define OFF_W1   (OFF_W0 + WBUF)
#define OFF_V0   (OFF_W1 + WBUF)
#define OFF_V1   (OFF_V0 + VBUF)
#define OFF_FEAT (OFF_V1 + VBUF)
#define OFF_XI   (OFF_FEAT + KF * FPITCH)
#define OFF_PART (OFF_XI + TMA * ND)
#define OFF_STAT (OFF_PART + 256)
#define SMEMA_FLOATS (OFF_STAT + 64)

__global__ void __launch_bounds__(512, 1) k_expert1(
    const float* __restrict__ expert_input,
    const float* __restrict__ freqs,
    const float* __restrict__ w1,
    const float* __restrict__ b1,
    const float* __restrict__ ln_g,
    const float* __restrict__ ln_b)
{
    int e = blockIdx.y;
    int cnt = g_cnt[e];
    int t0 = blockIdx.x * TMA;
    if (t0 >= cnt) return;

    extern __shared__ float sm[];
    uint32_t smb = (uint32_t)__cvta_generic_to_shared(sm);

    int tid  = threadIdx.x;
    int cg   = tid & 127;  // cols cg*4 .. cg*4+3
    int tg   = tid >> 7;   // tokens tg*8 .. tg*8+7
    int wid  = tid >> 5;
    int lane = tid & 31;

    // prefetch w/vec for d=0 into buffer 0
    {
        const float* wsrc = w1 + (size_t)(e * ND + 0) * WBUF;
        for (int i = tid; i < WBUF / 4; i += 512)
            cp16(smb + (OFF_W0 + i * 4) * 4, wsrc + i * 4);
        if (tid < 128)       cp16(smb + (OFF_V0 + tid * 4) * 4,        b1   + (size_t)(e * ND) * NH + tid * 4);
        else if (tid < 256)  cp16(smb + (OFF_V0 + 512 + (tid-128)*4)*4, ln_g + (size_t)(e * ND) * NH + (tid-128)*4);
        else if (tid < 384)  cp16(smb + (OFF_V0 + 1024 + (tid-256)*4)*4, ln_b + (size_t)(e * ND) * NH + (tid-256)*4);
        cp_commit();
    }

    {   // xi tile
        int t = tid >> 4, dd = tid & 15;
        int idx = t0 + t;
        int bb = g_tok[e][idx < cnt ? idx : (cnt - 1)];
        sm[OFF_XI + t * ND + dd] = expert_input[bb * ND + dd];
    }
    __syncthreads();

    float hacc[8][4];
#pragma unroll
    for (int i = 0; i < 8; i++)
#pragma unroll
        for (int j = 0; j < 4; j++) hacc[i][j] = 0.0f;

    for (int d = 0; d < ND; d++) {
        int buf = d & 1;
        int wof = buf ? OFF_W1 : OFF_W0;
        int vof = buf ? OFF_V1 : OFF_V0;

        cp_wait0();
        {   // fourier features for this d (transposed layout [f][token])
            int t = tid >> 4, f = tid & 15;
            float x  = sm[OFF_XI + t * ND + d];
            float fr = freqs[(e * ND + d) * NF + f];
            float ang = x * fr * 6.283185307179586f;
            float sv, cv;
            sincosf(ang, &sv, &cv);
            sm[OFF_FEAT + f * FPITCH + t]        = cv;
            sm[OFF_FEAT + (NF + f) * FPITCH + t] = sv;
            if (f == 0) sm[OFF_FEAT + 32 * FPITCH + t] = x;
        }
        __syncthreads();

        // prefetch next d
        if (d + 1 < ND) {
            int nb = (d + 1) & 1;
            int nwof = nb ? OFF_W1 : OFF_W0;
            int nvof = nb ? OFF_V1 : OFF_V0;
            const float* wsrc = w1 + (size_t)(e * ND + d + 1) * WBUF;
            for (int i = tid; i < WBUF / 4; i += 512)
                cp16(smb + (nwof + i * 4) * 4, wsrc + i * 4);
            if (tid < 128)       cp16(smb + (nvof + tid * 4) * 4,          b1   + (size_t)(e * ND + d + 1) * NH + tid * 4);
            else if (tid < 256)  cp16(smb + (nvof + 512 + (tid-128)*4)*4,  ln_g + (size_t)(e * ND + d + 1) * NH + (tid-128)*4);
            else if (tid < 384)  cp16(smb + (nvof + 1024 + (tid-256)*4)*4, ln_b + (size_t)(e * ND + d + 1) * NH + (tid-256)*4);
        }
        cp_commit();

        // GEMM (f32x2): v2[p][j] packs tokens (2p, 2p+1) for column cg*4+j
        u64 v2[4][4];
        {
            float4 b4 = *(const float4*)&sm[vof + cg * 4];
            u64 bd[4] = {pk2(b4.x, b4.x), pk2(b4.y, b4.y), pk2(b4.z, b4.z), pk2(b4.w, b4.w)};
#pragma unroll
            for (int p = 0; p < 4; p++)
#pragma unroll
                for (int j = 0; j < 4; j++) v2[p][j] = bd[j];
        }
#pragma unroll
        for (int f = 0; f < KF; f++) {
            float4 w4 = *(const float4*)&sm[wof + f * NH + cg * 4];
            u64 wd[4] = {pk2(w4.x, w4.x), pk2(w4.y, w4.y), pk2(w4.z, w4.z), pk2(w4.w, w4.w)};
            ulonglong2 fA = *(const ulonglong2*)&sm[OFF_FEAT + f * FPITCH + tg * 8];
            ulonglong2 fB = *(const ulonglong2*)&sm[OFF_FEAT + f * FPITCH + tg * 8 + 4];
            u64 fp[4] = {fA.x, fA.y, fB.x, fB.y};
#pragma unroll
            for (int p = 0; p < 4; p++) {
#pragma unroll
                for (int j = 0; j < 4; j++)
                    fma2(v2[p][j], wd[j], fp[p]);
            }
        }
        // unpack to scalar for LN/GELU
        float v[8][4];
#pragma unroll
        for (int p = 0; p < 4; p++)
#pragma unroll
            for (int j = 0; j < 4; j++)
                upk2(v2[p][j], v[2 * p][j], v[2 * p + 1][j]);

        // LN partial reduce
#pragma unroll
        for (int i = 0; i < 8; i++) {
            float s1 = v[i][0] + v[i][1] + v[i][2] + v[i][3];
            float s2 = fmaf(v[i][0], v[i][0], fmaf(v[i][1], v[i][1],
                       fmaf(v[i][2], v[i][2], v[i][3] * v[i][3])));
#pragma unroll
            for (int o = 16; o > 0; o >>= 1) {
                s1 += __shfl_xor_sync(0xffffffffu, s1, o);
                s2 += __shfl_xor_sync(0xffffffffu, s2, o);
            }
            if (lane == 0) {
                int tk = tg * 8 + i;
                sm[OFF_PART + tk * 4 + (wid & 3)]       = s1;
                sm[OFF_PART + 128 + tk * 4 + (wid & 3)] = s2;
            }
        }
        __syncthreads();
        if (tid < 32) {
            float a = sm[OFF_PART + tid * 4] + sm[OFF_PART + tid * 4 + 1]
                    + sm[OFF_PART + tid * 4 + 2] + sm[OFF_PART + tid * 4 + 3];
            float q = sm[OFF_PART + 128 + tid * 4] + sm[OFF_PART + 128 + tid * 4 + 1]
                    + sm[OFF_PART + 128 + tid * 4 + 2] + sm[OFF_PART + 128 + tid * 4 + 3];
            float mu  = a * (1.0f / 512.0f);
            float var = q * (1.0f / 512.0f) - mu * mu;
            sm[OFF_STAT + tid]      = mu;
            sm[OFF_STAT + 32 + tid] = rsqrtf(var + 1e-5f);
        }
        __syncthreads();

        // LN apply + GELU + accumulate
        {
            float4 g4 = *(const float4*)&sm[vof + 512 + cg * 4];
            float4 l4 = *(const float4*)&sm[vof + 1024 + cg * 4];
            float gj[4] = {g4.x, g4.y, g4.z, g4.w};
            float lj[4] = {l4.x, l4.y, l4.z, l4.w};
#pragma unroll
            for (int i = 0; i < 8; i++) {
                int tk = tg * 8 + i;
                float mu = sm[OFF_STAT + tk];
                float rs = sm[OFF_STAT + 32 + tk];
#pragma unroll
                for (int j = 0; j < 4; j++) {
                    float nx = fmaf((v[i][j] - mu) * rs, gj[j], lj[j]);
                    hacc[i][j] += gelu_tanh(nx);
                }
            }
        }
    }

#pragma unroll
    for (int i = 0; i < 8; i++) {
        int idx = t0 + tg * 8 + i;
        if (idx < cnt) {
            *(float4*)&g_h[e][idx][cg * 4] =
                make_float4(hacc[i][0], hacc[i][1], hacc[i][2], hacc[i][3]);
        }
    }
}

// ---------------- stage B: pipelined 128x128x16, f32x2 mainloop ----------
#define BM 128
#define BN 128
#define BK 16
#define NIT (NH / BK)   // 32

__global__ void __launch_bounds__(256, 2) k_out(
    const float* __restrict__ wo,
    const float* __restrict__ bo,
    float* __restrict__ out)
{
    int e = blockIdx.z;
    int cnt = g_cnt[e];
    int m0 = blockIdx.x * BM;
    if (m0 >= cnt) return;
    int n0 = blockIdx.y * BN;

    __shared__ float As[2][BK][BM];   // 16 KB
    __shared__ float Bs[2][BK][BN];   // 16 KB

    int tid = threadIdx.x;
    int tx = tid & 15;   // n: tx*8..+8
    int ty = tid >> 4;   // m: ty*8..+8

    // A: thread loads rows am, cols k0+aq..+8 (2 float4)
    int am = tid & 127;
    int aq = (tid >> 7) * 8;
    int amG = m0 + am;
    bool amOK = amG < cnt;
    const float* aptr = &g_h[e][amOK ? amG : 0][aq];
    // B: thread loads row bk, cols bc..+8 (2 float4)
    int bk = tid >> 4;
    int bc = (tid & 15) * 8;
    const float* bptr = wo + (size_t)e * NH * NH + (size_t)bk * NH + n0 + bc;

    float4 pa0, pa1, pb0, pb1;
    if (amOK) { pa0 = *(const float4*)(aptr);  pa1 = *(const float4*)(aptr + 4); }
    else      { pa0 = make_float4(0,0,0,0);    pa1 = pa0; }
    pb0 = *(const float4*)(bptr);
    pb1 = *(const float4*)(bptr + 4);
    {
        As[0][aq + 0][am] = pa0.x; As[0][aq + 1][am] = pa0.y;
        As[0][aq + 2][am] = pa0.z; As[0][aq + 3][am] = pa0.w;
        As[0][aq + 4][am] = pa1.x; As[0][aq + 5][am] = pa1.y;
        As[0][aq + 6][am] = pa1.z; As[0][aq + 7][am] = pa1.w;
        *(float4*)&Bs[0][bk][bc]     = pb0;
        *(float4*)&Bs[0][bk][bc + 4] = pb1;
    }
    __syncthreads();

    // acc2[i][q]: packed pair of output columns (2q, 2q+1) for row i
    u64 acc2[8][4];
#pragma unroll
    for (int i = 0; i < 8; i++)
#pragma unroll
        for (int q = 0; q < 4; q++) acc2[i][q] = 0ull;

    for (int it = 0; it < NIT; it++) {
        int cur = it & 1;
        if (it + 1 < NIT) {   // prefetch next tile into registers
            int k0 = (it + 1) * BK;
            if (amOK) { pa0 = *(const float4*)(aptr + k0);  pa1 = *(const float4*)(aptr + k0 + 4); }
            pb0 = *(const float4*)(bptr + (size_t)k0 * NH);
            pb1 = *(const float4*)(bptr + (size_t)k0 * NH + 4);
        }
#pragma unroll
        for (int kk = 0; kk < BK; kk++) {
            float4 a0 = *(const float4*)&As[cur][kk][ty * 8];
            float4 a1 = *(const float4*)&As[cur][kk][ty * 8 + 4];
            ulonglong2 bA = *(const ulonglong2*)&Bs[cur][kk][tx * 8];
            ulonglong2 bB = *(const ulonglong2*)&Bs[cur][kk][tx * 8 + 4];
            u64 b2[4] = {bA.x, bA.y, bB.x, bB.y};
            float aa[8] = {a0.x, a0.y, a0.z, a0.w, a1.x, a1.y, a1.z, a1.w};
#pragma unroll
            for (int i = 0; i < 8; i++) {
                u64 ad = pk2(aa[i], aa[i]);
#pragma unroll
                for (int q = 0; q < 4; q++)
                    fma2(acc2[i][q], ad, b2[q]);
            }
        }
        if (it + 1 < NIT) {
            int nxt = cur ^ 1;
            As[nxt][aq + 0][am] = pa0.x; As[nxt][aq + 1][am] = pa0.y;
            As[nxt][aq + 2][am] = pa0.z; As[nxt][aq + 3][am] = pa0.w;
            As[nxt][aq + 4][am] = pa1.x; As[nxt][aq + 5][am] = pa1.y;
            As[nxt][aq + 6][am] = pa1.z; As[nxt][aq + 7][am] = pa1.w;
            *(float4*)&Bs[nxt][bk][bc]     = pb0;
            *(float4*)&Bs[nxt][bk][bc + 4] = pb1;
            __syncthreads();
        }
    }

    float bv[8];
#pragma unroll
    for (int j = 0; j < 8; j++) bv[j] = bo[e * NH + n0 + tx * 8 + j];

#pragma unroll
    for (int i = 0; i < 8; i++) {
        int m = m0 + ty * 8 + i;
        if (m < cnt) {
            int bb = g_tok[e][m];
            float gv = g_gate[e][m];
            float* op = out + (size_t)bb * NH + n0 + tx * 8;
            float accv[8];
#pragma unroll
            for (int q = 0; q < 4; q++)
                upk2(acc2[i][q], accv[2 * q], accv[2 * q + 1]);
#pragma unroll
            for (int j = 0; j < 8; j++)
                atomicAdd(op + j, gv * (accv[j] + bv[j]));
        }
    }
}

// ---------------- launch ----------------
extern "C" void kernel_launch(void* const* d_in, const int* in_sizes, int n_in,
                              void* d_out, int out_size) {
    const float* gate_input   = (const float*)d_in[0];
    const float* expert_input = (const float*)d_in[1];
    const int*   task_bh      = (const int*)  d_in[2];
    const float* gate_w       = (const float*)d_in[3];
    const float* gate_b       = (const float*)d_in[4];
    const float* freqs        = (const float*)d_in[5];
    const float* w1           = (const float*)d_in[6];
    const float* b1           = (const float*)d_in[7];
    const float* ln_g         = (const float*)d_in[8];
    const float* ln_b         = (const float*)d_in[9];
    const float* wo           = (const float*)d_in[10];
    const float* bo           = (const float*)d_in[11];
    float* out = (float*)d_out;

    cudaFuncSetAttribute(k_expert1, cudaFuncAttributeMaxDynamicSharedMemorySize,
                         SMEMA_FLOATS * (int)sizeof(float));

    cudaMemsetAsync(d_out, 0, (size_t)out_size * sizeof(float), 0);
    k_init<<<1, 32>>>();
    k_gate<<<NB / 256, 256>>>(gate_input, task_bh, gate_w, gate_b);
    k_expert1<<<dim3(NB / TMA, NE), 512, SMEMA_FLOATS * (int)sizeof(float)>>>(
        expert_input, freqs, w1, b1, ln_g, ln_b);
    k_out<<<dim3(NB / BM, NH / BN, NE), 256>>>(wo, bo, out);
}

// round 15
// speedup vs baseline: 1.5220x; 1.0658x over previous
#include <cuda_runtime.h>
#include <math.h>
#include <stdint.h>

#define NB 8192   // batch
#define NE 8      // experts
#define ND 16     // robot_state_size
#define NF 16     // freq bands
#define NH 512    // hidden
#define NG 16     // gate input
#define KF 33     // 2F+1

typedef unsigned long long u64;

// ---------------- f32x2 packed helpers ----------------
__device__ __forceinline__ u64 pk2(float x, float y) {
    u64 r; asm("mov.b64 %0, {%1, %2};" : "=l"(r) : "f"(x), "f"(y)); return r;
}
__device__ __forceinline__ void upk2(u64 v, float& x, float& y) {
    asm("mov.b64 {%0, %1}, %2;" : "=f"(x), "=f"(y) : "l"(v));
}
__device__ __forceinline__ void fma2(u64& d, u64 a, u64 b) {
    asm("fma.rn.f32x2 %0, %1, %2, %0;" : "+l"(d) : "l"(a), "l"(b));
}

// ---------------- tf32 helpers ----------------
__device__ __forceinline__ uint32_t cvt_tf32(float x) {
    uint32_t r; asm("cvt.rna.tf32.f32 %0, %1;" : "=r"(r) : "f"(x)); return r;
}
__device__ __forceinline__ void mma_tf32(float* d, const uint32_t* a, const uint32_t* b) {
    asm volatile("mma.sync.aligned.m16n8k8.row.col.f32.tf32.tf32.f32 "
        "{%0,%1,%2,%3}, {%4,%5,%6,%7}, {%8,%9}, {%0,%1,%2,%3};"
        : "+f"(d[0]), "+f"(d[1]), "+f"(d[2]), "+f"(d[3])
        : "r"(a[0]), "r"(a[1]), "r"(a[2]), "r"(a[3]), "r"(b[0]), "r"(b[1]));
}

// ---------------- device scratch ----------------
__device__ int   g_cnt[NE];
__device__ int   g_tok[NE][NB];
__device__ float g_gate[NE][NB];
__device__ float g_h[NE][NB][NH];

// ---------------- init ----------------
__global__ void k_init() {
    if (threadIdx.x < NE) g_cnt[threadIdx.x] = 0;
}

// ---------------- gating ----------------
__global__ void k_gate(const float* __restrict__ gate_input,
                       const int*   __restrict__ task_ptr,
                       const float* __restrict__ gate_w,
                       const float* __restrict__ gate_b) {
    __shared__ float sw[NG * NE];
    __shared__ float sb[NE];
    int task = task_ptr[0];
    int tid = threadIdx.x;
    if (tid < NG * NE) sw[tid] = gate_w[task * NG * NE + tid];
    if (tid < NE)      sb[tid] = gate_b[task * NE + tid];
    __syncthreads();
    int b = blockIdx.x * blockDim.x + tid;
    if (b >= NB) return;
    float xi[NG];
#pragma unroll
    for (int g = 0; g < NG; g++) xi[g] = gate_input[b * NG + g];
    float lg[NE];
#pragma unroll
    for (int e = 0; e < NE; e++) {
        float a = sb[e];
#pragma unroll
        for (int g = 0; g < NG; g++) a = fmaf(xi[g], sw[g * NE + e], a);
        lg[e] = a;
    }
    int i1 = 0; float l1 = lg[0];
#pragma unroll
    for (int e = 1; e < NE; e++) if (lg[e] > l1) { l1 = lg[e]; i1 = e; }
    int i2 = -1; float l2 = -3.4e38f;
#pragma unroll
    for (int e = 0; e < NE; e++) if (e != i1 && lg[e] > l2) { l2 = lg[e]; i2 = e; }
    float t = expf(l2 - l1);
    float inv = 1.0f / (1.0f + t);
    int p1 = atomicAdd(&g_cnt[i1], 1);
    g_tok[i1][p1] = b; g_gate[i1][p1] = inv;
    int p2 = atomicAdd(&g_cnt[i2], 1);
    g_tok[i2][p2] = b; g_gate[i2][p2] = t * inv;
}

// ---------------- cp.async helpers ----------------
__device__ __forceinline__ void cp16(uint32_t dst, const void* src) {
    asm volatile("cp.async.ca.shared.global [%0], [%1], 16;\n" :: "r"(dst), "l"(src));
}
__device__ __forceinline__ void cp_commit() {
    asm volatile("cp.async.commit_group;\n");
}
__device__ __forceinline__ void cp_wait0() {
    asm volatile("cp.async.wait_group 0;\n");
}

// GELU via HW tanh
__device__ __forceinline__ float gelu_tanh(float x) {
    float x2 = x * x;
    float u = x * fmaf(0.0356774081f, x2, 0.7978845608f);
    float t;
    asm("tanh.approx.f32 %0, %1;" : "=f"(t) : "f"(u));
    return 0.5f * x * (1.0f + t);
}

// ---------------- stage A (unchanged from R12) ----------------
#define TMA 32
#define FPITCH 36
#define WBUF (KF * NH)
#define VBUF (3 * NH)
#define OFF_W0   0
#define OFF_W1   (OFF_W0 + WBUF)
#define OFF_V0   (OFF_W1 + WBUF)
#define OFF_V1   (OFF_V0 + VBUF)
#define OFF_FEAT (OFF_V1 + VBUF)
#define OFF_XI   (OFF_FEAT + KF * FPITCH)
#define OFF_PART (OFF_XI + TMA * ND)
#define OFF_STAT (OFF_PART + 256)
#define SMEMA_FLOATS (OFF_STAT + 64)

__global__ void __launch_bounds__(512, 1) k_expert1(
    const float* __restrict__ expert_input,
    const float* __restrict__ freqs,
    const float* __restrict__ w1,
    const float* __restrict__ b1,
    const float* __restrict__ ln_g,
    const float* __restrict__ ln_b)
{
    int e = blockIdx.y;
    int cnt = g_cnt[e];
    int t0 = blockIdx.x * TMA;
    if (t0 >= cnt) return;

    extern __shared__ float sm[];
    uint32_t smb = (uint32_t)__cvta_generic_to_shared(sm);

    int tid  = threadIdx.x;
    int cg   = tid & 127;
    int tg   = tid >> 7;
    int wid  = tid >> 5;
    int lane = tid & 31;

    {
        const float* wsrc = w1 + (size_t)(e * ND + 0) * WBUF;
        for (int i = tid; i < WBUF / 4; i += 512)
            cp16(smb + (OFF_W0 + i * 4) * 4, wsrc + i * 4);
        if (tid < 128)       cp16(smb + (OFF_V0 + tid * 4) * 4,        b1   + (size_t)(e * ND) * NH + tid * 4);
        else if (tid < 256)  cp16(smb + (OFF_V0 + 512 + (tid-128)*4)*4, ln_g + (size_t)(e * ND) * NH + (tid-128)*4);
        else if (tid < 384)  cp16(smb + (OFF_V0 + 1024 + (tid-256)*4)*4, ln_b + (size_t)(e * ND) * NH + (tid-256)*4);
        cp_commit();
    }

    {
        int t = tid >> 4, dd = tid & 15;
        int idx = t0 + t;
        int bb = g_tok[e][idx < cnt ? idx : (cnt - 1)];
        sm[OFF_XI + t * ND + dd] = expert_input[bb * ND + dd];
    }
    __syncthreads();

    float hacc[8][4];
#pragma unroll
    for (int i = 0; i < 8; i++)
#pragma unroll
        for (int j = 0; j < 4; j++) hacc[i][j] = 0.0f;

    for (int d = 0; d < ND; d++) {
        int buf = d & 1;
        int wof = buf ? OFF_W1 : OFF_W0;
        int vof = buf ? OFF_V1 : OFF_V0;

        cp_wait0();
        {
            int t = tid >> 4, f = tid & 15;
            float x  = sm[OFF_XI + t * ND + d];
            float fr = freqs[(e * ND + d) * NF + f];
            float ang = x * fr * 6.283185307179586f;
            float sv, cv;
            sincosf(ang, &sv, &cv);
            sm[OFF_FEAT + f * FPITCH + t]        = cv;
            sm[OFF_FEAT + (NF + f) * FPITCH + t] = sv;
            if (f == 0) sm[OFF_FEAT + 32 * FPITCH + t] = x;
        }
        __syncthreads();

        if (d + 1 < ND) {
            int nb = (d + 1) & 1;
            int nwof = nb ? OFF_W1 : OFF_W0;
            int nvof = nb ? OFF_V1 : OFF_V0;
            const float* wsrc = w1 + (size_t)(e * ND + d + 1) * WBUF;
            for (int i = tid; i < WBUF / 4; i += 512)
                cp16(smb + (nwof + i * 4) * 4, wsrc + i * 4);
            if (tid < 128)       cp16(smb + (nvof + tid * 4) * 4,          b1   + (size_t)(e * ND + d + 1) * NH + tid * 4);
            else if (tid < 256)  cp16(smb + (nvof + 512 + (tid-128)*4)*4,  ln_g + (size_t)(e * ND + d + 1) * NH + (tid-128)*4);
            else if (tid < 384)  cp16(smb + (nvof + 1024 + (tid-256)*4)*4, ln_b + (size_t)(e * ND + d + 1) * NH + (tid-256)*4);
        }
        cp_commit();

        u64 v2[4][4];
        {
            float4 b4 = *(const float4*)&sm[vof + cg * 4];
            u64 bd[4] = {pk2(b4.x, b4.x), pk2(b4.y, b4.y), pk2(b4.z, b4.z), pk2(b4.w, b4.w)};
#pragma unroll
            for (int p = 0; p < 4; p++)
#pragma unroll
                for (int j = 0; j < 4; j++) v2[p][j] = bd[j];
        }
#pragma unroll
        for (int f = 0; f < KF; f++) {
            float4 w4 = *(const float4*)&sm[wof + f * NH + cg * 4];
            u64 wd[4] = {pk2(w4.x, w4.x), pk2(w4.y, w4.y), pk2(w4.z, w4.z), pk2(w4.w, w4.w)};
            ulonglong2 fA = *(const ulonglong2*)&sm[OFF_FEAT + f * FPITCH + tg * 8];
            ulonglong2 fB = *(const ulonglong2*)&sm[OFF_FEAT + f * FPITCH + tg * 8 + 4];
            u64 fp[4] = {fA.x, fA.y, fB.x, fB.y};
#pragma unroll
            for (int p = 0; p < 4; p++) {
#pragma unroll
                for (int j = 0; j < 4; j++)
                    fma2(v2[p][j], wd[j], fp[p]);
            }
        }
        float v[8][4];
#pragma unroll
        for (int p = 0; p < 4; p++)
#pragma unroll
            for (int j = 0; j < 4; j++)
                upk2(v2[p][j], v[2 * p][j], v[2 * p + 1][j]);

#pragma unroll
        for (int i = 0; i < 8; i++) {
            float s1 = v[i][0] + v[i][1] + v[i][2] + v[i][3];
            float s2 = fmaf(v[i][0], v[i][0], fmaf(v[i][1], v[i][1],
                       fmaf(v[i][2], v[i][2], v[i][3] * v[i][3])));
#pragma unroll
            for (int o = 16; o > 0; o >>= 1) {
                s1 += __shfl_xor_sync(0xffffffffu, s1, o);
                s2 += __shfl_xor_sync(0xffffffffu, s2, o);
            }
            if (lane == 0) {
                int tk = tg * 8 + i;
                sm[OFF_PART + tk * 4 + (wid & 3)]       = s1;
                sm[OFF_PART + 128 + tk * 4 + (wid & 3)] = s2;
            }
        }
        __syncthreads();
        if (tid < 32) {
            float a = sm[OFF_PART + tid * 4] + sm[OFF_PART + tid * 4 + 1]
                    + sm[OFF_PART + tid * 4 + 2] + sm[OFF_PART + tid * 4 + 3];
            float q = sm[OFF_PART + 128 + tid * 4] + sm[OFF_PART + 128 + tid * 4 + 1]
                    + sm[OFF_PART + 128 + tid * 4 + 2] + sm[OFF_PART + 128 + tid * 4 + 3];
            float mu  = a * (1.0f / 512.0f);
            float var = q * (1.0f / 512.0f) - mu * mu;
            sm[OFF_STAT + tid]      = mu;
            sm[OFF_STAT + 32 + tid] = rsqrtf(var + 1e-5f);
        }
        __syncthreads();

        {
            float4 g4 = *(const float4*)&sm[vof + 512 + cg * 4];
            float4 l4 = *(const float4*)&sm[vof + 1024 + cg * 4];
            float gj[4] = {g4.x, g4.y, g4.z, g4.w};
            float lj[4] = {l4.x, l4.y, l4.z, l4.w};
#pragma unroll
            for (int i = 0; i < 8; i++) {
                int tk = tg * 8 + i;
                float mu = sm[OFF_STAT + tk];
                float rs = sm[OFF_STAT + 32 + tk];
#pragma unroll
                for (int j = 0; j < 4; j++) {
                    float nx = fmaf((v[i][j] - mu) * rs, gj[j], lj[j]);
                    hacc[i][j] += gelu_tanh(nx);
                }
            }
        }
    }

#pragma unroll
    for (int i = 0; i < 8; i++) {
        int idx = t0 + tg * 8 + i;
        if (idx < cnt) {
            *(float4*)&g_h[e][idx][cg * 4] =
                make_float4(hacc[i][0], hacc[i][1], hacc[i][2], hacc[i][3]);
        }
    }
}

// ---------------- stage B: tf32 tensor-core GEMM (3xTF32) -----------------
// CTA tile 128x64, 8 warps in 4(m) x 2(n), warp tile 32x32.
#define BM2 128
#define BN2 64
#define BK2 16
#define NIT2 (NH / BK2)     // 32
#define STRA 136            // A tile row stride (bank = 8t+g, conflict-free)
#define STRB 72             // B tile row stride
#define ATSZ (BK2 * STRA)   // 2176 u32 per buffer
#define BTSZ (BK2 * STRB)   // 1152 u32 per buffer
#define SMEMB_U32 (2*ATSZ*2 + 2*BTSZ*2)   // Ab,As double-buffered + Bb,Bs

__global__ void __launch_bounds__(256, 2) k_out(
    const float* __restrict__ wo,
    const float* __restrict__ bo,
    float* __restrict__ out)
{
    int e = blockIdx.z;
    int cnt = g_cnt[e];
    int m0 = blockIdx.x * BM2;
    if (m0 >= cnt) return;
    int n0 = blockIdx.y * BN2;

    extern __shared__ uint32_t smu[];
    uint32_t* Ab  = smu;                 // [2][ATSZ]
    uint32_t* Asm = Ab  + 2 * ATSZ;      // [2][ATSZ]
    uint32_t* Bb  = Asm + 2 * ATSZ;      // [2][BTSZ]
    uint32_t* Bsm = Bb  + 2 * BTSZ;      // [2][BTSZ]

    int tid  = threadIdx.x;
    int w    = tid >> 5;
    int lane = tid & 31;
    int wm   = w & 3;        // m block (0..3) of 32 rows
    int wn   = w >> 2;       // n block (0..1) of 32 cols
    int g    = lane >> 2;    // group id (0..7)
    int t    = lane & 3;     // thread in group (0..3)

    // loaders
    int am = tid & 127;               // A row
    int aq = (tid >> 7) * 8;          // A k-offset (0 or 8)
    int amG = m0 + am;
    bool amOK = amG < cnt;
    const float* aptr = &g_h[e][amOK ? amG : 0][aq];
    int bk = tid >> 4;                // B k-row (0..15)
    int bc = (tid & 15) * 4;          // B col chunk
    const float* bptr = wo + (size_t)e * NH * NH + (size_t)bk * NH + n0 + bc;

    float av[8];
    float4 bv4;

    // prologue: load k0=0
    if (amOK) {
        float4 x0 = *(const float4*)(aptr);
        float4 x1 = *(const float4*)(aptr + 4);
        av[0]=x0.x; av[1]=x0.y; av[2]=x0.z; av[3]=x0.w;
        av[4]=x1.x; av[5]=x1.y; av[6]=x1.z; av[7]=x1.w;
    } else {
#pragma unroll
        for (int j = 0; j < 8; j++) av[j] = 0.0f;
    }
    bv4 = *(const float4*)(bptr);
    {
#pragma unroll
        for (int j = 0; j < 8; j++) {
            uint32_t bg = cvt_tf32(av[j]);
            float sf = av[j] - __uint_as_float(bg);
            Ab [(aq + j) * STRA + am] = bg;
            Asm[(aq + j) * STRA + am] = cvt_tf32(sf);
        }
        float bf[4] = {bv4.x, bv4.y, bv4.z, bv4.w};
        uint32_t gb[4], sb[4];
#pragma unroll
        for (int j = 0; j < 4; j++) {
            gb[j] = cvt_tf32(bf[j]);
            sb[j] = cvt_tf32(bf[j] - __uint_as_float(gb[j]));
        }
        *(uint4*)&Bb [bk * STRB + bc] = make_uint4(gb[0], gb[1], gb[2], gb[3]);
        *(uint4*)&Bsm[bk * STRB + bc] = make_uint4(sb[0], sb[1], sb[2], sb[3]);
    }
    __syncthreads();

    float d[2][4][4];
#pragma unroll
    for (int mi = 0; mi < 2; mi++)
#pragma unroll
        for (int nj = 0; nj < 4; nj++)
#pragma unroll
            for (int r = 0; r < 4; r++) d[mi][nj][r] = 0.0f;

    for (int it = 0; it < NIT2; it++) {
        int cur = it & 1;
        if (it + 1 < NIT2) {   // prefetch next k tile into registers
            int k0 = (it + 1) * BK2;
            if (amOK) {
                float4 x0 = *(const float4*)(aptr + k0);
                float4 x1 = *(const float4*)(aptr + k0 + 4);
                av[0]=x0.x; av[1]=x0.y; av[2]=x0.z; av[3]=x0.w;
                av[4]=x1.x; av[5]=x1.y; av[6]=x1.z; av[7]=x1.w;
            }
            bv4 = *(const float4*)(bptr + (size_t)k0 * NH);
        }

        const uint32_t* pAb = Ab  + cur * ATSZ;
        const uint32_t* pAs = Asm + cur * ATSZ;
        const uint32_t* pBb = Bb  + cur * BTSZ;
        const uint32_t* pBs = Bsm + cur * BTSZ;

#pragma unroll
        for (int kh = 0; kh < 2; kh++) {
            int ks = kh * 8;
            // B fragments for all 4 n8 blocks
            uint32_t fbb[4][2], fbs[4][2];
#pragma unroll
            for (int nj = 0; nj < 4; nj++) {
                int cb = wn * 32 + nj * 8 + g;
                fbb[nj][0] = pBb[(ks + t) * STRB + cb];
                fbb[nj][1] = pBb[(ks + t + 4) * STRB + cb];
                fbs[nj][0] = pBs[(ks + t) * STRB + cb];
                fbs[nj][1] = pBs[(ks + t + 4) * STRB + cb];
            }
#pragma unroll
            for (int mi = 0; mi < 2; mi++) {
                int rb = wm * 32 + mi * 16 + g;
                uint32_t fab[4], fas[4];
                fab[0] = pAb[(ks + t) * STRA + rb];
                fab[1] = pAb[(ks + t) * STRA + rb + 8];
                fab[2] = pAb[(ks + t + 4) * STRA + rb];
                fab[3] = pAb[(ks + t + 4) * STRA + rb + 8];
                fas[0] = pAs[(ks + t) * STRA + rb];
                fas[1] = pAs[(ks + t) * STRA + rb + 8];
                fas[2] = pAs[(ks + t + 4) * STRA + rb];
                fas[3] = pAs[(ks + t + 4) * STRA + rb + 8];
#pragma unroll
                for (int nj = 0; nj < 4; nj++) {
                    mma_tf32(d[mi][nj], fab, fbb[nj]);   // big*big
                    mma_tf32(d[mi][nj], fab, fbs[nj]);   // big*small
                    mma_tf32(d[mi][nj], fas, fbb[nj]);   // small*big
                }
            }
        }

        if (it + 1 < NIT2) {
            int nxt = cur ^ 1;
            uint32_t* nAb = Ab  + nxt * ATSZ;
            uint32_t* nAs = Asm + nxt * ATSZ;
            uint32_t* nBb = Bb  + nxt * BTSZ;
            uint32_t* nBs = Bsm + nxt * BTSZ;
#pragma unroll
            for (int j = 0; j < 8; j++) {
                uint32_t bg = cvt_tf32(av[j]);
                float sf = av[j] - __uint_as_float(bg);
                nAb[(aq + j) * STRA + am] = bg;
                nAs[(aq + j) * STRA + am] = cvt_tf32(sf);
            }
            float bf[4] = {bv4.x, bv4.y, bv4.z, bv4.w};
            uint32_t gb[4], sb2[4];
#pragma unroll
            for (int j = 0; j < 4; j++) {
                gb[j]  = cvt_tf32(bf[j]);
                sb2[j] = cvt_tf32(bf[j] - __uint_as_float(gb[j]));
            }
            *(uint4*)&nBb[bk * STRB + bc] = make_uint4(gb[0], gb[1], gb[2], gb[3]);
            *(uint4*)&nBs[bk * STRB + bc] = make_uint4(sb2[0], sb2[1], sb2[2], sb2[3]);
            __syncthreads();
        }
    }

    // epilogue: D rows -> gated atomic scatter
    const float* bop = bo + e * NH;
#pragma unroll
    for (int mi = 0; mi < 2; mi++) {
        int r0 = m0 + wm * 32 + mi * 16 + g;
        int r1 = r0 + 8;
        int tok0 = 0, tok1 = 0; float gv0 = 0.f, gv1 = 0.f;
        bool ok0 = r0 < cnt, ok1 = r1 < cnt;
        if (ok0) { tok0 = g_tok[e][r0]; gv0 = g_gate[e][r0]; }
        if (ok1) { tok1 = g_tok[e][r1]; gv1 = g_gate[e][r1]; }
#pragma unroll
        for (int nj = 0; nj < 4; nj++) {
            int c = n0 + wn * 32 + nj * 8 + 2 * t;
            float b0v = bop[c], b1v = bop[c + 1];
            if (ok0) {
                float* op = out + (size_t)tok0 * NH + c;
                atomicAdd(op,     gv0 * (d[mi][nj][0] + b0v));
                atomicAdd(op + 1, gv0 * (d[mi][nj][1] + b1v));
            }
            if (ok1) {
                float* op = out + (size_t)tok1 * NH + c;
                atomicAdd(op,     gv1 * (d[mi][nj][2] + b0v));
                atomicAdd(op + 1, gv1 * (d[mi][nj][3] + b1v));
            }
        }
    }
}

// ---------------- launch ----------------
extern "C" void kernel_launch(void* const* d_in, const int* in_sizes, int n_in,
                              void* d_out, int out_size) {
    const float* gate_input   = (const float*)d_in[0];
    const float* expert_input = (const float*)d_in[1];
    const int*   task_bh      = (const int*)  d_in[2];
    const float* gate_w       = (const float*)d_in[3];
    const float* gate_b       = (const float*)d_in[4];
    const float* freqs        = (const float*)d_in[5];
    const float* w1           = (const float*)d_in[6];
    const float* b1           = (const float*)d_in[7];
    const float* ln_g         = (const float*)d_in[8];
    const float* ln_b         = (const float*)d_in[9];
    const float* wo           = (const float*)d_in[10];
    const float* bo           = (const float*)d_in[11];
    float* out = (float*)d_out;

    cudaFuncSetAttribute(k_expert1, cudaFuncAttributeMaxDynamicSharedMemorySize,
                         SMEMA_FLOATS * (int)sizeof(float));
    cudaFuncSetAttribute(k_out, cudaFuncAttributeMaxDynamicSharedMemorySize,
                         SMEMB_U32 * (int)sizeof(uint32_t));

    cudaMemsetAsync(d_out, 0, (size_t)out_size * sizeof(float), 0);
    k_init<<<1, 32>>>();
    k_gate<<<NB / 256, 256>>>(gate_input, task_bh, gate_w, gate_b);
    k_expert1<<<dim3(NB / TMA, NE), 512, SMEMA_FLOATS * (int)sizeof(float)>>>(
        expert_input, freqs, w1, b1, ln_g, ln_b);
    k_out<<<dim3(NB / BM2, NH / BN2, NE), 256, SMEMB_U32 * (int)sizeof(uint32_t)>>>(
        wo, bo, out);
}